// round 14
// baseline (speedup 1.0000x reference)
#include <cuda_runtime.h>
#include <cuda_bf16.h>
#include <stdint.h>

// Fused self-attention (Q=K=V=x), B=8, N=4096, C=64, fp32 in/out.
// out = gamma * softmax(x x^T) x + x
// Single-split bf16 HMMA flash attention. Fixed per-row softmax reference
// m_i = ||x_i||^2; consistent weights -> errors cancel; diagonal repaired
// exactly in epilogue. Schraudolph bf16 exp (no MUFU); l via ones-MMA.
// R14: 4-buffer K ring, one cp.async-wait + one barrier per TWO tiles.

#define NTOK   4096
#define CDIM   64
#define BM     128
#define BN     64
#define NTILES (NTOK / BN)
#define BATCH  8

// Schraudolph constants: p_bf16_bits = round(184.665*(s-m) + 16249)
#define EXPA   184.6650558f
#define MAGICF 12582912.0f            // 1.5 * 2^23
#define EXPB   (MAGICF + 16249.0f)

// ---------------- device scratch ----------------
__device__ __nv_bfloat16 g_xh[BATCH * (size_t)NTOK * CDIM];
__device__ float         g_sd[BATCH * NTOK];

// ---------------- helpers ----------------
__device__ __forceinline__ uint32_t smem_u32(const void* p) {
    uint32_t a;
    asm("{ .reg .u64 t; cvta.to.shared.u64 t, %1; cvt.u32.u64 %0, t; }" : "=r"(a) : "l"(p));
    return a;
}
__device__ __forceinline__ uint32_t pkbf(float lo, float hi) {
    uint32_t r;
    asm("cvt.rn.satfinite.bf16x2.f32 %0, %1, %2;" : "=r"(r) : "f"(hi), "f"(lo));
    return r;
}
__device__ __forceinline__ uint32_t prmt5410(uint32_t a, uint32_t b) {
    uint32_t r;
    asm("prmt.b32 %0, %1, %2, 0x5410;" : "=r"(r) : "r"(a), "r"(b));
    return r;
}
__device__ __forceinline__ float lo2f(uint32_t u) { return __uint_as_float(u << 16); }
__device__ __forceinline__ float hi2f(uint32_t u) { return __uint_as_float(u & 0xFFFF0000u); }

#define SWZ(o) ((o) ^ (((o) >> 3) & 0x70))

#define LDSM4(r0, r1, r2, r3, addr) \
    asm volatile("ldmatrix.sync.aligned.m8n8.x4.shared.b16 {%0,%1,%2,%3}, [%4];" \
                 : "=r"(r0), "=r"(r1), "=r"(r2), "=r"(r3) : "r"(addr))
#define LDSM4T(r0, r1, r2, r3, addr) \
    asm volatile("ldmatrix.sync.aligned.m8n8.x4.trans.shared.b16 {%0,%1,%2,%3}, [%4];" \
                 : "=r"(r0), "=r"(r1), "=r"(r2), "=r"(r3) : "r"(addr))
#define MMA(d, a0, a1, a2, a3, b0, b1) \
    asm volatile("mma.sync.aligned.m16n8k16.row.col.f32.bf16.bf16.f32 " \
                 "{%0,%1,%2,%3}, {%4,%5,%6,%7}, {%8,%9}, {%0,%1,%2,%3};" \
                 : "+f"((d)[0]), "+f"((d)[1]), "+f"((d)[2]), "+f"((d)[3]) \
                 : "r"(a0), "r"(a1), "r"(a2), "r"(a3), "r"(b0), "r"(b1))

__device__ __forceinline__ void cp16(uint32_t dst, const void* src) {
    asm volatile("cp.async.cg.shared.global [%0], [%1], 16;" :: "r"(dst), "l"(src) : "memory");
}
#define CP_COMMIT() asm volatile("cp.async.commit_group;" ::: "memory")
#define CP_WAIT0()  asm volatile("cp.async.wait_group 0;" ::: "memory")

// ---------------- smem layout ----------------
#define QH_OFF 0            // 16 KB : Q tile, SW128
#define KH_OFF 16384        // 4 x 8 KB : K tile ring
#define SMEM_TOTAL 49152

// ---------------- prep: bf16 hi + selfdot ----------------
__global__ __launch_bounds__(256) void prep_kernel(const float* __restrict__ x) {
    __shared__ float sx[64][65];
    const int b   = blockIdx.y;
    const int n0  = blockIdx.x * 64;
    const int tid = threadIdx.x;
    const float* xb = x + ((size_t)b * NTOK + n0) * CDIM;

    #pragma unroll
    for (int i = 0; i < 4; ++i) {
        int ch  = tid + 256 * i;
        int row = ch >> 4, g = ch & 15;
        float4 v = *(const float4*)(xb + row * CDIM + 4 * g);
        sx[row][4 * g + 0] = v.x; sx[row][4 * g + 1] = v.y;
        sx[row][4 * g + 2] = v.z; sx[row][4 * g + 3] = v.w;
        uint32_t hp0 = pkbf(v.x, v.y), hp1 = pkbf(v.z, v.w);
        size_t idx = ((size_t)b * NTOK + n0 + row) * CDIM + 4 * g;
        *(uint2*)(g_xh + idx) = make_uint2(hp0, hp1);
    }
    __syncthreads();
    if (tid < 64) {
        float s = 0.f;
        #pragma unroll
        for (int c = 0; c < 64; ++c) { float v = sx[tid][c]; s += v * v; }
        g_sd[b * NTOK + n0 + tid] = s;
    }
}

// ---------------- main attention kernel ----------------
__global__ __launch_bounds__(128, 2)
void attn_mma_kernel(const float* __restrict__ x, const float* __restrict__ gamma,
                     float* __restrict__ out) {
    extern __shared__ char smem[];
    const uint32_t sb = smem_u32(smem);
    const int tid = threadIdx.x, w = tid >> 5, lane = tid & 31;
    const int b = blockIdx.y, m0 = blockIdx.x * BM;
    const __nv_bfloat16* xh = g_xh + (size_t)b * NTOK * CDIM;

    // ---- Q tile, SW128-swizzled ----
    #pragma unroll
    for (int i = 0; i < 8; ++i) {
        int ch = tid + 128 * i;
        int row = ch >> 3, g = ch & 7;
        *(uint4*)(smem + QH_OFF + SWZ(row * 128 + 16 * g)) =
            *(const uint4*)(xh + (size_t)(m0 + row) * CDIM + 8 * g);
    }
    // ---- K tiles 0,1 via cp.async (one group) ----
    const int prow = tid >> 3, pg = tid & 7;
    #pragma unroll
    for (int u = 0; u < 2; ++u) {
        #pragma unroll
        for (int i = 0; i < 4; ++i) {
            int row = prow + 16 * i;
            cp16(sb + KH_OFF + (uint32_t)(u * 8192) + SWZ(row * 128 + 16 * pg),
                 xh + (size_t)(u * BN + row) * CDIM + 8 * pg);
        }
    }
    CP_COMMIT();

    float o[2][8][4];
    #pragma unroll
    for (int mf = 0; mf < 2; ++mf)
        #pragma unroll
        for (int j = 0; j < 8; ++j)
            #pragma unroll
            for (int v = 0; v < 4; ++v) o[mf][j][v] = 0.f;
    float lacc[2][4];
    #pragma unroll
    for (int mf = 0; mf < 2; ++mf)
        #pragma unroll
        for (int v = 0; v < 4; ++v) lacc[mf][v] = 0.f;

    const int r = lane >> 2;
    float bmA[2], bmB[2];
    bmA[0] = EXPB - g_sd[b * NTOK + m0 + w * 32 + r]      * EXPA;
    bmB[0] = EXPB - g_sd[b * NTOK + m0 + w * 32 + r + 8]  * EXPA;
    bmA[1] = EXPB - g_sd[b * NTOK + m0 + w * 32 + 16 + r] * EXPA;
    bmB[1] = EXPB - g_sd[b * NTOK + m0 + w * 32 + 24 + r] * EXPA;

    // diagonal-capture
    float cA[2] = {0.f, 0.f}, cB[2] = {0.f, 0.f};
    const int  td   = (m0 + w * 32) >> 6;
    const int  fdA0 = (w * 4) & 7;
    const int  fdA1 = (w * 4 + 2) & 7;
    const bool cmatch = (2 * (lane & 3)) == (r & 6);
    const int  vsel   = r & 1;

#define CAPTURE(mf_, f_, p0_, p1_)                                       \
    if (dtile && cmatch) {                                               \
        const int fda_ = (mf_) ? fdA1 : fdA0;                            \
        if ((f_) == fda_)     cA[mf_] = vsel ? hi2f(p0_) : lo2f(p0_);    \
        if ((f_) == fda_ + 1) cB[mf_] = vsel ? hi2f(p1_) : lo2f(p1_);    \
    }

    const int qrow0 = w * 32 + (lane & 15);
    const uint32_t aq_sel = (uint32_t)((lane >> 4) * 16);
    const uint32_t aq_b0 = (uint32_t)(qrow0 * 128);
    const uint32_t aq_x0 = (uint32_t)((qrow0 << 4) & 0x70);
    const uint32_t aq_b1 = (uint32_t)((qrow0 + 16) * 128);
    const uint32_t aq_x1 = (uint32_t)(((qrow0 + 16) << 4) & 0x70);
    const uint32_t krl    = (uint32_t)(((((lane >> 4) & 1) * 8) + (lane & 7)) * 128);
    const uint32_t bk_sel = (uint32_t)(((lane >> 3) & 1) * 16);
    const uint32_t kx     = (uint32_t)((lane & 7) << 4);
    const uint32_t vrl  = (uint32_t)((lane & 15) * 128);
    const uint32_t jsel = (uint32_t)(((lane >> 4) & 1) * 16);
    const uint32_t ONES = 0x3F803F80u;   // bf16x2 {1.0, 1.0}

    CP_WAIT0();
    __syncthreads();

    for (int t0 = 0; t0 < NTILES; t0 += 2) {
        // ---- prefetch tiles t0+2, t0+3 into ring slots (read 2 steps ago) ----
        if (t0 + 2 < NTILES) {
            #pragma unroll
            for (int u = 0; u < 2; ++u) {
                const int tn = t0 + 2 + u;
                const uint32_t nb = KH_OFF + (uint32_t)(tn & 3) * 8192;
                const __nv_bfloat16* kh = xh + (size_t)tn * BN * CDIM;
                #pragma unroll
                for (int i = 0; i < 4; ++i) {
                    int row = prow + 16 * i;
                    cp16(sb + nb + SWZ(row * 128 + 16 * pg), kh + (size_t)row * CDIM + 8 * pg);
                }
            }
        }
        CP_COMMIT();

        // ---- process tiles t0 and t0+1 ----
        #pragma unroll
        for (int u = 0; u < 2; ++u) {
            const int t = t0 + u;
            const uint32_t KHc = KH_OFF + (uint32_t)(t & 3) * 8192;
            const bool dtile = (t == td);

            float s[2][8][4];
            #pragma unroll
            for (int mf = 0; mf < 2; ++mf)
                #pragma unroll
                for (int f = 0; f < 8; ++f)
                    #pragma unroll
                    for (int v = 0; v < 4; ++v) s[mf][f][v] = 0.f;

            // ---- S = Q K^T ----
            #pragma unroll
            for (int kc = 0; kc < 4; ++kc) {
                const uint32_t csel = (uint32_t)(kc * 32) + aq_sel;
                uint32_t q0h[4], q1h[4];
                LDSM4(q0h[0], q0h[1], q0h[2], q0h[3], sb + QH_OFF + aq_b0 + (csel ^ aq_x0));
                LDSM4(q1h[0], q1h[1], q1h[2], q1h[3], sb + QH_OFF + aq_b1 + (csel ^ aq_x1));
                const uint32_t colk = ((uint32_t)(kc * 32) + bk_sel) ^ kx;
                #pragma unroll
                for (int h = 0; h < 2; ++h) {
                    uint32_t kh[8];
                    const uint32_t ka = sb + KHc + (uint32_t)(h * 4096) + krl + colk;
                    LDSM4(kh[0], kh[1], kh[2], kh[3], ka);
                    LDSM4(kh[4], kh[5], kh[6], kh[7], ka + 2048);
                    #pragma unroll
                    for (int j = 0; j < 4; ++j) MMA(s[0][h * 4 + j], q0h[0], q0h[1], q0h[2], q0h[3], kh[2 * j], kh[2 * j + 1]);
                    #pragma unroll
                    for (int j = 0; j < 4; ++j) MMA(s[1][h * 4 + j], q1h[0], q1h[1], q1h[2], q1h[3], kh[2 * j], kh[2 * j + 1]);
                }
            }

            // ---- exp via Schraudolph (fma/alu only) ----
            uint32_t ph[2][8][2];
            #pragma unroll
            for (int mf = 0; mf < 2; ++mf)
                #pragma unroll
                for (int f = 0; f < 8; ++f) {
                    float y0 = fmaxf(fmaf(s[mf][f][0], EXPA, bmA[mf]), MAGICF);
                    float y1 = fmaxf(fmaf(s[mf][f][1], EXPA, bmA[mf]), MAGICF);
                    float y2 = fmaxf(fmaf(s[mf][f][2], EXPA, bmB[mf]), MAGICF);
                    float y3 = fmaxf(fmaf(s[mf][f][3], EXPA, bmB[mf]), MAGICF);
                    ph[mf][f][0] = prmt5410(__float_as_uint(y0), __float_as_uint(y1));
                    ph[mf][f][1] = prmt5410(__float_as_uint(y2), __float_as_uint(y3));
                    CAPTURE(mf, f, ph[mf][f][0], ph[mf][f][1]);
                }

            // ---- O += P V ; l += P * ones ----
            #pragma unroll
            for (int kc = 0; kc < 4; ++kc) {
                const uint32_t a00 = ph[0][2 * kc][0], a01 = ph[0][2 * kc][1];
                const uint32_t a02 = ph[0][2 * kc + 1][0], a03 = ph[0][2 * kc + 1][1];
                const uint32_t a10 = ph[1][2 * kc][0], a11 = ph[1][2 * kc][1];
                const uint32_t a12 = ph[1][2 * kc + 1][0], a13 = ph[1][2 * kc + 1][1];
                MMA(lacc[0], a00, a01, a02, a03, ONES, ONES);
                MMA(lacc[1], a10, a11, a12, a13, ONES, ONES);
                const uint32_t vbase = sb + KHc + (uint32_t)(kc * 2048) + vrl;
                #pragma unroll
                for (int h = 0; h < 2; ++h) {
                    uint32_t vh[8];
                    const uint32_t cAo = ((uint32_t)(h * 64) + jsel) ^ kx;
                    const uint32_t cBo = ((uint32_t)(h * 64 + 32) + jsel) ^ kx;
                    LDSM4T(vh[0], vh[1], vh[2], vh[3], vbase + cAo);
                    LDSM4T(vh[4], vh[5], vh[6], vh[7], vbase + cBo);
                    #pragma unroll
                    for (int j = 0; j < 4; ++j) MMA(o[0][h * 4 + j], a00, a01, a02, a03, vh[2 * j], vh[2 * j + 1]);
                    #pragma unroll
                    for (int j = 0; j < 4; ++j) MMA(o[1][h * 4 + j], a10, a11, a12, a13, vh[2 * j], vh[2 * j + 1]);
                }
            }
        }

        CP_WAIT0();
        __syncthreads();   // one barrier per 2 tiles
    }

    // ---- epilogue ----
    const float gm = gamma[0];
    const int c0 = 2 * (lane & 3);
    #pragma unroll
    for (int mf = 0; mf < 2; ++mf) {
        const float la = lacc[mf][0];
        const float lb = lacc[mf][2];
        float a1 = cA[mf], b1 = cB[mf];
        #pragma unroll
        for (int off = 1; off <= 2; off <<= 1) {
            a1 += __shfl_xor_sync(0xffffffffu, a1, off);
            b1 += __shfl_xor_sync(0xffffffffu, b1, off);
        }
        const float sA = gm / la, sB = gm / lb;
        const size_t rowA = ((size_t)b * NTOK + m0 + w * 32 + mf * 16 + r) * CDIM;
        const size_t rowB = rowA + 8 * CDIM;
        #pragma unroll
        for (int j = 0; j < 8; ++j) {
            const int c = j * 8 + c0;
            float2 xa  = *(const float2*)(x + rowA + c);
            float2 xb2 = *(const float2*)(x + rowB + c);
            uint32_t pa = pkbf(xa.x, xa.y);
            uint32_t pb = pkbf(xb2.x, xb2.y);
            float oax = o[mf][j][0] + a1 * (xa.x  - lo2f(pa));
            float oay = o[mf][j][1] + a1 * (xa.y  - hi2f(pa));
            float obx = o[mf][j][2] + b1 * (xb2.x - lo2f(pb));
            float oby = o[mf][j][3] + b1 * (xb2.y - hi2f(pb));
            float2 oa, ob;
            oa.x = sA * oax + xa.x;  oa.y = sA * oay + xa.y;
            ob.x = sB * obx + xb2.x; ob.y = sB * oby + xb2.y;
            *(float2*)(out + rowA + c) = oa;
            *(float2*)(out + rowB + c) = ob;
        }
    }
}

// ---------------- launch ----------------
extern "C" void kernel_launch(void* const* d_in, const int* in_sizes, int n_in,
                              void* d_out, int out_size) {
    const float* x     = (const float*)d_in[0];
    const float* gamma = (const float*)d_in[1];
    float* out         = (float*)d_out;

    cudaFuncSetAttribute(attn_mma_kernel, cudaFuncAttributeMaxDynamicSharedMemorySize, SMEM_TOTAL);

    prep_kernel<<<dim3(NTOK / 64, BATCH), 256>>>(x);
    attn_mma_kernel<<<dim3(NTOK / BM, BATCH), 128, SMEM_TOTAL>>>(x, gamma, out);
}

// round 15
// speedup vs baseline: 1.0270x; 1.0270x over previous
#include <cuda_runtime.h>
#include <cuda_bf16.h>
#include <stdint.h>

// Fused self-attention (Q=K=V=x), B=8, N=4096, C=64, fp32 in/out.
// out = gamma * softmax(x x^T) x + x
// Single-split bf16 HMMA flash attention. Fixed per-row softmax reference
// m_i = ||x_i||^2; consistent weights -> errors cancel; diagonal repaired
// exactly in epilogue. Schraudolph bf16 exp (no MUFU); l via ones-MMA.
// R15 = R13 + Q fragments hoisted into registers (tile-invariant), cutting
// LDSM4 per warp-tile 24 -> 16 (smem crossbar was ~78% of tensor time).

#define NTOK   4096
#define CDIM   64
#define BM     128
#define BN     64
#define NTILES (NTOK / BN)
#define BATCH  8

// Schraudolph constants: p_bf16_bits = round(184.665*(s-m) + 16249)
#define EXPA   184.6650558f
#define MAGICF 12582912.0f            // 1.5 * 2^23
#define EXPB   (MAGICF + 16249.0f)

// ---------------- device scratch ----------------
__device__ __nv_bfloat16 g_xh[BATCH * (size_t)NTOK * CDIM];
__device__ float         g_sd[BATCH * NTOK];

// ---------------- helpers ----------------
__device__ __forceinline__ uint32_t smem_u32(const void* p) {
    uint32_t a;
    asm("{ .reg .u64 t; cvta.to.shared.u64 t, %1; cvt.u32.u64 %0, t; }" : "=r"(a) : "l"(p));
    return a;
}
__device__ __forceinline__ uint32_t pkbf(float lo, float hi) {
    uint32_t r;
    asm("cvt.rn.satfinite.bf16x2.f32 %0, %1, %2;" : "=r"(r) : "f"(hi), "f"(lo));
    return r;
}
__device__ __forceinline__ uint32_t prmt5410(uint32_t a, uint32_t b) {
    uint32_t r;
    asm("prmt.b32 %0, %1, %2, 0x5410;" : "=r"(r) : "r"(a), "r"(b));
    return r;
}
__device__ __forceinline__ float lo2f(uint32_t u) { return __uint_as_float(u << 16); }
__device__ __forceinline__ float hi2f(uint32_t u) { return __uint_as_float(u & 0xFFFF0000u); }

#define SWZ(o) ((o) ^ (((o) >> 3) & 0x70))

#define LDSM4(r0, r1, r2, r3, addr) \
    asm volatile("ldmatrix.sync.aligned.m8n8.x4.shared.b16 {%0,%1,%2,%3}, [%4];" \
                 : "=r"(r0), "=r"(r1), "=r"(r2), "=r"(r3) : "r"(addr))
#define LDSM4T(r0, r1, r2, r3, addr) \
    asm volatile("ldmatrix.sync.aligned.m8n8.x4.trans.shared.b16 {%0,%1,%2,%3}, [%4];" \
                 : "=r"(r0), "=r"(r1), "=r"(r2), "=r"(r3) : "r"(addr))
#define MMA(d, a0, a1, a2, a3, b0, b1) \
    asm volatile("mma.sync.aligned.m16n8k16.row.col.f32.bf16.bf16.f32 " \
                 "{%0,%1,%2,%3}, {%4,%5,%6,%7}, {%8,%9}, {%0,%1,%2,%3};" \
                 : "+f"((d)[0]), "+f"((d)[1]), "+f"((d)[2]), "+f"((d)[3]) \
                 : "r"(a0), "r"(a1), "r"(a2), "r"(a3), "r"(b0), "r"(b1))

__device__ __forceinline__ void cp16(uint32_t dst, const void* src) {
    asm volatile("cp.async.cg.shared.global [%0], [%1], 16;" :: "r"(dst), "l"(src) : "memory");
}
#define CP_COMMIT() asm volatile("cp.async.commit_group;" ::: "memory")
#define CP_WAIT0()  asm volatile("cp.async.wait_group 0;" ::: "memory")

// ---------------- smem layout ----------------
#define QH_OFF 0            // 16 KB : Q tile, SW128 (read once into registers)
#define KH_OFF 16384        // 2 x 8 KB : K tile double buffer
#define SMEM_TOTAL 32768

// ---------------- prep: bf16 hi + selfdot ----------------
__global__ __launch_bounds__(256) void prep_kernel(const float* __restrict__ x) {
    __shared__ float sx[64][65];
    const int b   = blockIdx.y;
    const int n0  = blockIdx.x * 64;
    const int tid = threadIdx.x;
    const float* xb = x + ((size_t)b * NTOK + n0) * CDIM;

    #pragma unroll
    for (int i = 0; i < 4; ++i) {
        int ch  = tid + 256 * i;
        int row = ch >> 4, g = ch & 15;
        float4 v = *(const float4*)(xb + row * CDIM + 4 * g);
        sx[row][4 * g + 0] = v.x; sx[row][4 * g + 1] = v.y;
        sx[row][4 * g + 2] = v.z; sx[row][4 * g + 3] = v.w;
        uint32_t hp0 = pkbf(v.x, v.y), hp1 = pkbf(v.z, v.w);
        size_t idx = ((size_t)b * NTOK + n0 + row) * CDIM + 4 * g;
        *(uint2*)(g_xh + idx) = make_uint2(hp0, hp1);
    }
    __syncthreads();
    if (tid < 64) {
        float s = 0.f;
        #pragma unroll
        for (int c = 0; c < 64; ++c) { float v = sx[tid][c]; s += v * v; }
        g_sd[b * NTOK + n0 + tid] = s;
    }
}

// ---------------- main attention kernel ----------------
__global__ __launch_bounds__(128, 2)
void attn_mma_kernel(const float* __restrict__ x, const float* __restrict__ gamma,
                     float* __restrict__ out) {
    extern __shared__ char smem[];
    const uint32_t sb = smem_u32(smem);
    const int tid = threadIdx.x, w = tid >> 5, lane = tid & 31;
    const int b = blockIdx.y, m0 = blockIdx.x * BM;
    const __nv_bfloat16* xh = g_xh + (size_t)b * NTOK * CDIM;

    // ---- Q tile, SW128-swizzled ----
    #pragma unroll
    for (int i = 0; i < 8; ++i) {
        int ch = tid + 128 * i;
        int row = ch >> 3, g = ch & 7;
        *(uint4*)(smem + QH_OFF + SWZ(row * 128 + 16 * g)) =
            *(const uint4*)(xh + (size_t)(m0 + row) * CDIM + 8 * g);
    }
    // ---- K tile 0 ----
    const int prow = tid >> 3, pg = tid & 7;
    #pragma unroll
    for (int i = 0; i < 4; ++i) {
        int row = prow + 16 * i;
        *(uint4*)(smem + KH_OFF + SWZ(row * 128 + 16 * pg)) =
            *(const uint4*)(xh + (size_t)row * CDIM + 8 * pg);
    }

    float o[2][8][4];
    #pragma unroll
    for (int mf = 0; mf < 2; ++mf)
        #pragma unroll
        for (int j = 0; j < 8; ++j)
            #pragma unroll
            for (int v = 0; v < 4; ++v) o[mf][j][v] = 0.f;
    float lacc[2][4];
    #pragma unroll
    for (int mf = 0; mf < 2; ++mf)
        #pragma unroll
        for (int v = 0; v < 4; ++v) lacc[mf][v] = 0.f;

    const int r = lane >> 2;
    float bmA[2], bmB[2];
    bmA[0] = EXPB - g_sd[b * NTOK + m0 + w * 32 + r]      * EXPA;
    bmB[0] = EXPB - g_sd[b * NTOK + m0 + w * 32 + r + 8]  * EXPA;
    bmA[1] = EXPB - g_sd[b * NTOK + m0 + w * 32 + 16 + r] * EXPA;
    bmB[1] = EXPB - g_sd[b * NTOK + m0 + w * 32 + 24 + r] * EXPA;

    // diagonal-capture
    float cA[2] = {0.f, 0.f}, cB[2] = {0.f, 0.f};
    const int  td   = (m0 + w * 32) >> 6;
    const int  fdA0 = (w * 4) & 7;
    const int  fdA1 = (w * 4 + 2) & 7;
    const bool cmatch = (2 * (lane & 3)) == (r & 6);
    const int  vsel   = r & 1;

#define CAPTURE(mf_, f_, p0_, p1_)                                       \
    if (dtile && cmatch) {                                               \
        const int fda_ = (mf_) ? fdA1 : fdA0;                            \
        if ((f_) == fda_)     cA[mf_] = vsel ? hi2f(p0_) : lo2f(p0_);    \
        if ((f_) == fda_ + 1) cB[mf_] = vsel ? hi2f(p1_) : lo2f(p1_);    \
    }

    const int qrow0 = w * 32 + (lane & 15);
    const uint32_t aq_sel = (uint32_t)((lane >> 4) * 16);
    const uint32_t aq_b0 = (uint32_t)(qrow0 * 128);
    const uint32_t aq_x0 = (uint32_t)((qrow0 << 4) & 0x70);
    const uint32_t aq_b1 = (uint32_t)((qrow0 + 16) * 128);
    const uint32_t aq_x1 = (uint32_t)(((qrow0 + 16) << 4) & 0x70);
    const uint32_t krl    = (uint32_t)(((((lane >> 4) & 1) * 8) + (lane & 7)) * 128);
    const uint32_t bk_sel = (uint32_t)(((lane >> 3) & 1) * 16);
    const uint32_t kx     = (uint32_t)((lane & 7) << 4);
    const uint32_t vrl  = (uint32_t)((lane & 15) * 128);
    const uint32_t jsel = (uint32_t)(((lane >> 4) & 1) * 16);
    const uint32_t ONES = 0x3F803F80u;   // bf16x2 {1.0, 1.0}

    __syncthreads();

    // ---- hoist Q fragments into registers (tile-invariant) ----
    uint32_t qf[4][2][4];
    #pragma unroll
    for (int kc = 0; kc < 4; ++kc) {
        const uint32_t csel = (uint32_t)(kc * 32) + aq_sel;
        LDSM4(qf[kc][0][0], qf[kc][0][1], qf[kc][0][2], qf[kc][0][3],
              sb + QH_OFF + aq_b0 + (csel ^ aq_x0));
        LDSM4(qf[kc][1][0], qf[kc][1][1], qf[kc][1][2], qf[kc][1][3],
              sb + QH_OFF + aq_b1 + (csel ^ aq_x1));
    }

    for (int t = 0; t < NTILES; ++t) {
        const uint32_t KHc = KH_OFF + (uint32_t)(t & 1) * 8192;
        const bool dtile = (t == td);

        // ---- prefetch next K tile ----
        if (t + 1 < NTILES) {
            const uint32_t nb = KH_OFF + (uint32_t)((t + 1) & 1) * 8192;
            const __nv_bfloat16* kh = xh + (size_t)(t + 1) * BN * CDIM;
            #pragma unroll
            for (int i = 0; i < 4; ++i) {
                int row = prow + 16 * i;
                cp16(sb + nb + SWZ(row * 128 + 16 * pg), kh + (size_t)row * CDIM + 8 * pg);
            }
        }
        CP_COMMIT();

        float s[2][8][4];
        #pragma unroll
        for (int mf = 0; mf < 2; ++mf)
            #pragma unroll
            for (int f = 0; f < 8; ++f)
                #pragma unroll
                for (int v = 0; v < 4; ++v) s[mf][f][v] = 0.f;

        // ---- S = Q K^T (Q from registers) ----
        #pragma unroll
        for (int kc = 0; kc < 4; ++kc) {
            const uint32_t colk = ((uint32_t)(kc * 32) + bk_sel) ^ kx;
            #pragma unroll
            for (int h = 0; h < 2; ++h) {
                uint32_t kh[8];
                const uint32_t ka = sb + KHc + (uint32_t)(h * 4096) + krl + colk;
                LDSM4(kh[0], kh[1], kh[2], kh[3], ka);
                LDSM4(kh[4], kh[5], kh[6], kh[7], ka + 2048);
                #pragma unroll
                for (int j = 0; j < 4; ++j)
                    MMA(s[0][h * 4 + j], qf[kc][0][0], qf[kc][0][1], qf[kc][0][2], qf[kc][0][3],
                        kh[2 * j], kh[2 * j + 1]);
                #pragma unroll
                for (int j = 0; j < 4; ++j)
                    MMA(s[1][h * 4 + j], qf[kc][1][0], qf[kc][1][1], qf[kc][1][2], qf[kc][1][3],
                        kh[2 * j], kh[2 * j + 1]);
            }
        }

        // ---- exp via Schraudolph (fma/alu only) ----
        uint32_t ph[2][8][2];
        #pragma unroll
        for (int mf = 0; mf < 2; ++mf)
            #pragma unroll
            for (int f = 0; f < 8; ++f) {
                float y0 = fmaxf(fmaf(s[mf][f][0], EXPA, bmA[mf]), MAGICF);
                float y1 = fmaxf(fmaf(s[mf][f][1], EXPA, bmA[mf]), MAGICF);
                float y2 = fmaxf(fmaf(s[mf][f][2], EXPA, bmB[mf]), MAGICF);
                float y3 = fmaxf(fmaf(s[mf][f][3], EXPA, bmB[mf]), MAGICF);
                ph[mf][f][0] = prmt5410(__float_as_uint(y0), __float_as_uint(y1));
                ph[mf][f][1] = prmt5410(__float_as_uint(y2), __float_as_uint(y3));
                CAPTURE(mf, f, ph[mf][f][0], ph[mf][f][1]);
            }

        // ---- O += P V ; l += P * ones ----
        #pragma unroll
        for (int kc = 0; kc < 4; ++kc) {
            const uint32_t a00 = ph[0][2 * kc][0], a01 = ph[0][2 * kc][1];
            const uint32_t a02 = ph[0][2 * kc + 1][0], a03 = ph[0][2 * kc + 1][1];
            const uint32_t a10 = ph[1][2 * kc][0], a11 = ph[1][2 * kc][1];
            const uint32_t a12 = ph[1][2 * kc + 1][0], a13 = ph[1][2 * kc + 1][1];
            MMA(lacc[0], a00, a01, a02, a03, ONES, ONES);
            MMA(lacc[1], a10, a11, a12, a13, ONES, ONES);
            const uint32_t vbase = sb + KHc + (uint32_t)(kc * 2048) + vrl;
            #pragma unroll
            for (int h = 0; h < 2; ++h) {
                uint32_t vh[8];
                const uint32_t cAo = ((uint32_t)(h * 64) + jsel) ^ kx;
                const uint32_t cBo = ((uint32_t)(h * 64 + 32) + jsel) ^ kx;
                LDSM4T(vh[0], vh[1], vh[2], vh[3], vbase + cAo);
                LDSM4T(vh[4], vh[5], vh[6], vh[7], vbase + cBo);
                #pragma unroll
                for (int j = 0; j < 4; ++j) MMA(o[0][h * 4 + j], a00, a01, a02, a03, vh[2 * j], vh[2 * j + 1]);
                #pragma unroll
                for (int j = 0; j < 4; ++j) MMA(o[1][h * 4 + j], a10, a11, a12, a13, vh[2 * j], vh[2 * j + 1]);
            }
        }

        CP_WAIT0();
        __syncthreads();
    }

    // ---- epilogue ----
    const float gm = gamma[0];
    const int c0 = 2 * (lane & 3);
    #pragma unroll
    for (int mf = 0; mf < 2; ++mf) {
        const float la = lacc[mf][0];
        const float lb = lacc[mf][2];
        float a1 = cA[mf], b1 = cB[mf];
        #pragma unroll
        for (int off = 1; off <= 2; off <<= 1) {
            a1 += __shfl_xor_sync(0xffffffffu, a1, off);
            b1 += __shfl_xor_sync(0xffffffffu, b1, off);
        }
        const float sA = gm / la, sB = gm / lb;
        const size_t rowA = ((size_t)b * NTOK + m0 + w * 32 + mf * 16 + r) * CDIM;
        const size_t rowB = rowA + 8 * CDIM;
        #pragma unroll
        for (int j = 0; j < 8; ++j) {
            const int c = j * 8 + c0;
            float2 xa  = *(const float2*)(x + rowA + c);
            float2 xb2 = *(const float2*)(x + rowB + c);
            uint32_t pa = pkbf(xa.x, xa.y);
            uint32_t pb = pkbf(xb2.x, xb2.y);
            float oax = o[mf][j][0] + a1 * (xa.x  - lo2f(pa));
            float oay = o[mf][j][1] + a1 * (xa.y  - hi2f(pa));
            float obx = o[mf][j][2] + b1 * (xb2.x - lo2f(pb));
            float oby = o[mf][j][3] + b1 * (xb2.y - hi2f(pb));
            float2 oa, ob;
            oa.x = sA * oax + xa.x;  oa.y = sA * oay + xa.y;
            ob.x = sB * obx + xb2.x; ob.y = sB * oby + xb2.y;
            *(float2*)(out + rowA + c) = oa;
            *(float2*)(out + rowB + c) = ob;
        }
    }
}

// ---------------- launch ----------------
extern "C" void kernel_launch(void* const* d_in, const int* in_sizes, int n_in,
                              void* d_out, int out_size) {
    const float* x     = (const float*)d_in[0];
    const float* gamma = (const float*)d_in[1];
    float* out         = (float*)d_out;

    cudaFuncSetAttribute(attn_mma_kernel, cudaFuncAttributeMaxDynamicSharedMemorySize, SMEM_TOTAL);

    prep_kernel<<<dim3(NTOK / 64, BATCH), 256>>>(x);
    attn_mma_kernel<<<dim3(NTOK / BM, BATCH), 128, SMEM_TOTAL>>>(x, gamma, out);
}

// round 16
// speedup vs baseline: 1.1563x; 1.1259x over previous
#include <cuda_runtime.h>
#include <cuda_bf16.h>
#include <stdint.h>

// Fused self-attention (Q=K=V=x), B=8, N=4096, C=64, fp32 in/out.
// out = gamma * softmax(x x^T) x + x
// Single-split bf16 HMMA flash attention. Fixed per-row softmax reference
// m_i = ||x_i||^2; consistent weights -> errors cancel; diagonal repaired
// exactly in epilogue. Schraudolph bf16 exp; l via ones-MMA; Q hoisted.
// R16: per-warp adaptive tile skip — if every weight in the (warp x ktile)
// block is < ~1e-9 (bounded total effect <= 5.4e-6 relative, realized ~1e-25),
// skip exp + PV + l entirely. S is always computed (it IS the safety check).

#define NTOK   4096
#define CDIM   64
#define BM     128
#define BN     64
#define NTILES (NTOK / BN)
#define BATCH  8

// Schraudolph constants: p_bf16_bits = round(184.665*(s-m) + 16249)
#define EXPA   184.6650558f
#define MAGICF 12582912.0f            // 1.5 * 2^23
#define EXPB   (MAGICF + 16249.0f)
// active-tile threshold: bf16 bits of ~1e-9 (weights below are skippable)
#define YTHR   (MAGICF + 12400.0f)

// ---------------- device scratch ----------------
__device__ __nv_bfloat16 g_xh[BATCH * (size_t)NTOK * CDIM];
__device__ float         g_sd[BATCH * NTOK];

// ---------------- helpers ----------------
__device__ __forceinline__ uint32_t smem_u32(const void* p) {
    uint32_t a;
    asm("{ .reg .u64 t; cvta.to.shared.u64 t, %1; cvt.u32.u64 %0, t; }" : "=r"(a) : "l"(p));
    return a;
}
__device__ __forceinline__ uint32_t pkbf(float lo, float hi) {
    uint32_t r;
    asm("cvt.rn.satfinite.bf16x2.f32 %0, %1, %2;" : "=r"(r) : "f"(hi), "f"(lo));
    return r;
}
__device__ __forceinline__ uint32_t prmt5410(uint32_t a, uint32_t b) {
    uint32_t r;
    asm("prmt.b32 %0, %1, %2, 0x5410;" : "=r"(r) : "r"(a), "r"(b));
    return r;
}
__device__ __forceinline__ float lo2f(uint32_t u) { return __uint_as_float(u << 16); }
__device__ __forceinline__ float hi2f(uint32_t u) { return __uint_as_float(u & 0xFFFF0000u); }

#define SWZ(o) ((o) ^ (((o) >> 3) & 0x70))

#define LDSM4(r0, r1, r2, r3, addr) \
    asm volatile("ldmatrix.sync.aligned.m8n8.x4.shared.b16 {%0,%1,%2,%3}, [%4];" \
                 : "=r"(r0), "=r"(r1), "=r"(r2), "=r"(r3) : "r"(addr))
#define LDSM4T(r0, r1, r2, r3, addr) \
    asm volatile("ldmatrix.sync.aligned.m8n8.x4.trans.shared.b16 {%0,%1,%2,%3}, [%4];" \
                 : "=r"(r0), "=r"(r1), "=r"(r2), "=r"(r3) : "r"(addr))
#define MMA(d, a0, a1, a2, a3, b0, b1) \
    asm volatile("mma.sync.aligned.m16n8k16.row.col.f32.bf16.bf16.f32 " \
                 "{%0,%1,%2,%3}, {%4,%5,%6,%7}, {%8,%9}, {%0,%1,%2,%3};" \
                 : "+f"((d)[0]), "+f"((d)[1]), "+f"((d)[2]), "+f"((d)[3]) \
                 : "r"(a0), "r"(a1), "r"(a2), "r"(a3), "r"(b0), "r"(b1))

__device__ __forceinline__ void cp16(uint32_t dst, const void* src) {
    asm volatile("cp.async.cg.shared.global [%0], [%1], 16;" :: "r"(dst), "l"(src) : "memory");
}
#define CP_COMMIT() asm volatile("cp.async.commit_group;" ::: "memory")
#define CP_WAIT0()  asm volatile("cp.async.wait_group 0;" ::: "memory")

// ---------------- smem layout ----------------
#define QH_OFF 0            // 16 KB : Q tile, SW128 (read once into registers)
#define KH_OFF 16384        // 2 x 8 KB : K tile double buffer
#define SMEM_TOTAL 32768

// ---------------- prep: bf16 hi + selfdot ----------------
__global__ __launch_bounds__(256) void prep_kernel(const float* __restrict__ x) {
    __shared__ float sx[64][65];
    const int b   = blockIdx.y;
    const int n0  = blockIdx.x * 64;
    const int tid = threadIdx.x;
    const float* xb = x + ((size_t)b * NTOK + n0) * CDIM;

    #pragma unroll
    for (int i = 0; i < 4; ++i) {
        int ch  = tid + 256 * i;
        int row = ch >> 4, g = ch & 15;
        float4 v = *(const float4*)(xb + row * CDIM + 4 * g);
        sx[row][4 * g + 0] = v.x; sx[row][4 * g + 1] = v.y;
        sx[row][4 * g + 2] = v.z; sx[row][4 * g + 3] = v.w;
        uint32_t hp0 = pkbf(v.x, v.y), hp1 = pkbf(v.z, v.w);
        size_t idx = ((size_t)b * NTOK + n0 + row) * CDIM + 4 * g;
        *(uint2*)(g_xh + idx) = make_uint2(hp0, hp1);
    }
    __syncthreads();
    if (tid < 64) {
        float s = 0.f;
        #pragma unroll
        for (int c = 0; c < 64; ++c) { float v = sx[tid][c]; s += v * v; }
        g_sd[b * NTOK + n0 + tid] = s;
    }
}

// ---------------- main attention kernel ----------------
__global__ __launch_bounds__(128, 2)
void attn_mma_kernel(const float* __restrict__ x, const float* __restrict__ gamma,
                     float* __restrict__ out) {
    extern __shared__ char smem[];
    const uint32_t sb = smem_u32(smem);
    const int tid = threadIdx.x, w = tid >> 5, lane = tid & 31;
    const int b = blockIdx.y, m0 = blockIdx.x * BM;
    const __nv_bfloat16* xh = g_xh + (size_t)b * NTOK * CDIM;

    // ---- Q tile, SW128-swizzled ----
    #pragma unroll
    for (int i = 0; i < 8; ++i) {
        int ch = tid + 128 * i;
        int row = ch >> 3, g = ch & 7;
        *(uint4*)(smem + QH_OFF + SWZ(row * 128 + 16 * g)) =
            *(const uint4*)(xh + (size_t)(m0 + row) * CDIM + 8 * g);
    }
    // ---- K tile 0 ----
    const int prow = tid >> 3, pg = tid & 7;
    #pragma unroll
    for (int i = 0; i < 4; ++i) {
        int row = prow + 16 * i;
        *(uint4*)(smem + KH_OFF + SWZ(row * 128 + 16 * pg)) =
            *(const uint4*)(xh + (size_t)row * CDIM + 8 * pg);
    }

    float o[2][8][4];
    #pragma unroll
    for (int mf = 0; mf < 2; ++mf)
        #pragma unroll
        for (int j = 0; j < 8; ++j)
            #pragma unroll
            for (int v = 0; v < 4; ++v) o[mf][j][v] = 0.f;
    float lacc[2][4];
    #pragma unroll
    for (int mf = 0; mf < 2; ++mf)
        #pragma unroll
        for (int v = 0; v < 4; ++v) lacc[mf][v] = 0.f;

    const int r = lane >> 2;
    float bmA[2], bmB[2];
    bmA[0] = EXPB - g_sd[b * NTOK + m0 + w * 32 + r]      * EXPA;
    bmB[0] = EXPB - g_sd[b * NTOK + m0 + w * 32 + r + 8]  * EXPA;
    bmA[1] = EXPB - g_sd[b * NTOK + m0 + w * 32 + 16 + r] * EXPA;
    bmB[1] = EXPB - g_sd[b * NTOK + m0 + w * 32 + 24 + r] * EXPA;

    // diagonal-capture
    float cA[2] = {0.f, 0.f}, cB[2] = {0.f, 0.f};
    const int  td   = (m0 + w * 32) >> 6;
    const int  fdA0 = (w * 4) & 7;
    const int  fdA1 = (w * 4 + 2) & 7;
    const bool cmatch = (2 * (lane & 3)) == (r & 6);
    const int  vsel   = r & 1;

#define CAPTURE(mf_, f_, p0_, p1_)                                       \
    if (dtile && cmatch) {                                               \
        const int fda_ = (mf_) ? fdA1 : fdA0;                            \
        if ((f_) == fda_)     cA[mf_] = vsel ? hi2f(p0_) : lo2f(p0_);    \
        if ((f_) == fda_ + 1) cB[mf_] = vsel ? hi2f(p1_) : lo2f(p1_);    \
    }

    const int qrow0 = w * 32 + (lane & 15);
    const uint32_t aq_sel = (uint32_t)((lane >> 4) * 16);
    const uint32_t aq_b0 = (uint32_t)(qrow0 * 128);
    const uint32_t aq_x0 = (uint32_t)((qrow0 << 4) & 0x70);
    const uint32_t aq_b1 = (uint32_t)((qrow0 + 16) * 128);
    const uint32_t aq_x1 = (uint32_t)(((qrow0 + 16) << 4) & 0x70);
    const uint32_t krl    = (uint32_t)(((((lane >> 4) & 1) * 8) + (lane & 7)) * 128);
    const uint32_t bk_sel = (uint32_t)(((lane >> 3) & 1) * 16);
    const uint32_t kx     = (uint32_t)((lane & 7) << 4);
    const uint32_t vrl  = (uint32_t)((lane & 15) * 128);
    const uint32_t jsel = (uint32_t)(((lane >> 4) & 1) * 16);
    const uint32_t ONES = 0x3F803F80u;   // bf16x2 {1.0, 1.0}

    __syncthreads();

    // ---- hoist Q fragments into registers (tile-invariant) ----
    uint32_t qf[4][2][4];
    #pragma unroll
    for (int kc = 0; kc < 4; ++kc) {
        const uint32_t csel = (uint32_t)(kc * 32) + aq_sel;
        LDSM4(qf[kc][0][0], qf[kc][0][1], qf[kc][0][2], qf[kc][0][3],
              sb + QH_OFF + aq_b0 + (csel ^ aq_x0));
        LDSM4(qf[kc][1][0], qf[kc][1][1], qf[kc][1][2], qf[kc][1][3],
              sb + QH_OFF + aq_b1 + (csel ^ aq_x1));
    }

    for (int t = 0; t < NTILES; ++t) {
        const uint32_t KHc = KH_OFF + (uint32_t)(t & 1) * 8192;
        const bool dtile = (t == td);

        // ---- prefetch next K tile ----
        if (t + 1 < NTILES) {
            const uint32_t nb = KH_OFF + (uint32_t)((t + 1) & 1) * 8192;
            const __nv_bfloat16* kh = xh + (size_t)(t + 1) * BN * CDIM;
            #pragma unroll
            for (int i = 0; i < 4; ++i) {
                int row = prow + 16 * i;
                cp16(sb + nb + SWZ(row * 128 + 16 * pg), kh + (size_t)row * CDIM + 8 * pg);
            }
        }
        CP_COMMIT();

        float s[2][8][4];
        #pragma unroll
        for (int mf = 0; mf < 2; ++mf)
            #pragma unroll
            for (int f = 0; f < 8; ++f)
                #pragma unroll
                for (int v = 0; v < 4; ++v) s[mf][f][v] = 0.f;

        // ---- S = Q K^T (Q from registers) ----
        #pragma unroll
        for (int kc = 0; kc < 4; ++kc) {
            const uint32_t colk = ((uint32_t)(kc * 32) + bk_sel) ^ kx;
            #pragma unroll
            for (int h = 0; h < 2; ++h) {
                uint32_t kh[8];
                const uint32_t ka = sb + KHc + (uint32_t)(h * 4096) + krl + colk;
                LDSM4(kh[0], kh[1], kh[2], kh[3], ka);
                LDSM4(kh[4], kh[5], kh[6], kh[7], ka + 2048);
                #pragma unroll
                for (int j = 0; j < 4; ++j)
                    MMA(s[0][h * 4 + j], qf[kc][0][0], qf[kc][0][1], qf[kc][0][2], qf[kc][0][3],
                        kh[2 * j], kh[2 * j + 1]);
                #pragma unroll
                for (int j = 0; j < 4; ++j)
                    MMA(s[1][h * 4 + j], qf[kc][1][0], qf[kc][1][1], qf[kc][1][2], qf[kc][1][3],
                        kh[2 * j], kh[2 * j + 1]);
            }
        }

        // ---- warp-level activity check: max over groups of (s*EXPA + bm) ----
        float gmx[2][2];
        #pragma unroll
        for (int mf = 0; mf < 2; ++mf) {
            float ma = s[mf][0][0], mb = s[mf][0][2];
            ma = fmaxf(ma, s[mf][0][1]);
            mb = fmaxf(mb, s[mf][0][3]);
            #pragma unroll
            for (int f = 1; f < 8; ++f) {
                ma = fmaxf(ma, fmaxf(s[mf][f][0], s[mf][f][1]));
                mb = fmaxf(mb, fmaxf(s[mf][f][2], s[mf][f][3]));
            }
            gmx[mf][0] = fmaf(ma, EXPA, bmA[mf]);
            gmx[mf][1] = fmaf(mb, EXPA, bmB[mf]);
        }
        float wmax = fmaxf(fmaxf(gmx[0][0], gmx[0][1]), fmaxf(gmx[1][0], gmx[1][1]));
        #pragma unroll
        for (int off = 16; off; off >>= 1)
            wmax = fmaxf(wmax, __shfl_xor_sync(0xffffffffu, wmax, off));

        if (wmax >= YTHR) {
            // ---- exp via Schraudolph (fma/alu only) ----
            uint32_t ph[2][8][2];
            #pragma unroll
            for (int mf = 0; mf < 2; ++mf)
                #pragma unroll
                for (int f = 0; f < 8; ++f) {
                    float y0 = fmaxf(fmaf(s[mf][f][0], EXPA, bmA[mf]), MAGICF);
                    float y1 = fmaxf(fmaf(s[mf][f][1], EXPA, bmA[mf]), MAGICF);
                    float y2 = fmaxf(fmaf(s[mf][f][2], EXPA, bmB[mf]), MAGICF);
                    float y3 = fmaxf(fmaf(s[mf][f][3], EXPA, bmB[mf]), MAGICF);
                    ph[mf][f][0] = prmt5410(__float_as_uint(y0), __float_as_uint(y1));
                    ph[mf][f][1] = prmt5410(__float_as_uint(y2), __float_as_uint(y3));
                    CAPTURE(mf, f, ph[mf][f][0], ph[mf][f][1]);
                }

            // ---- O += P V ; l += P * ones ----
            #pragma unroll
            for (int kc = 0; kc < 4; ++kc) {
                const uint32_t a00 = ph[0][2 * kc][0], a01 = ph[0][2 * kc][1];
                const uint32_t a02 = ph[0][2 * kc + 1][0], a03 = ph[0][2 * kc + 1][1];
                const uint32_t a10 = ph[1][2 * kc][0], a11 = ph[1][2 * kc][1];
                const uint32_t a12 = ph[1][2 * kc + 1][0], a13 = ph[1][2 * kc + 1][1];
                MMA(lacc[0], a00, a01, a02, a03, ONES, ONES);
                MMA(lacc[1], a10, a11, a12, a13, ONES, ONES);
                const uint32_t vbase = sb + KHc + (uint32_t)(kc * 2048) + vrl;
                #pragma unroll
                for (int h = 0; h < 2; ++h) {
                    uint32_t vh[8];
                    const uint32_t cAo = ((uint32_t)(h * 64) + jsel) ^ kx;
                    const uint32_t cBo = ((uint32_t)(h * 64 + 32) + jsel) ^ kx;
                    LDSM4T(vh[0], vh[1], vh[2], vh[3], vbase + cAo);
                    LDSM4T(vh[4], vh[5], vh[6], vh[7], vbase + cBo);
                    #pragma unroll
                    for (int j = 0; j < 4; ++j) MMA(o[0][h * 4 + j], a00, a01, a02, a03, vh[2 * j], vh[2 * j + 1]);
                    #pragma unroll
                    for (int j = 0; j < 4; ++j) MMA(o[1][h * 4 + j], a10, a11, a12, a13, vh[2 * j], vh[2 * j + 1]);
                }
            }
        }

        CP_WAIT0();
        __syncthreads();
    }

    // ---- epilogue ----
    const float gm = gamma[0];
    const int c0 = 2 * (lane & 3);
    #pragma unroll
    for (int mf = 0; mf < 2; ++mf) {
        const float la = lacc[mf][0];
        const float lb = lacc[mf][2];
        float a1 = cA[mf], b1 = cB[mf];
        #pragma unroll
        for (int off = 1; off <= 2; off <<= 1) {
            a1 += __shfl_xor_sync(0xffffffffu, a1, off);
            b1 += __shfl_xor_sync(0xffffffffu, b1, off);
        }
        const float sA = gm / la, sB = gm / lb;
        const size_t rowA = ((size_t)b * NTOK + m0 + w * 32 + mf * 16 + r) * CDIM;
        const size_t rowB = rowA + 8 * CDIM;
        #pragma unroll
        for (int j = 0; j < 8; ++j) {
            const int c = j * 8 + c0;
            float2 xa  = *(const float2*)(x + rowA + c);
            float2 xb2 = *(const float2*)(x + rowB + c);
            uint32_t pa = pkbf(xa.x, xa.y);
            uint32_t pb = pkbf(xb2.x, xb2.y);
            float oax = o[mf][j][0] + a1 * (xa.x  - lo2f(pa));
            float oay = o[mf][j][1] + a1 * (xa.y  - hi2f(pa));
            float obx = o[mf][j][2] + b1 * (xb2.x - lo2f(pb));
            float oby = o[mf][j][3] + b1 * (xb2.y - hi2f(pb));
            float2 oa, ob;
            oa.x = sA * oax + xa.x;  oa.y = sA * oay + xa.y;
            ob.x = sB * obx + xb2.x; ob.y = sB * oby + xb2.y;
            *(float2*)(out + rowA + c) = oa;
            *(float2*)(out + rowB + c) = ob;
        }
    }
}

// ---------------- launch ----------------
extern "C" void kernel_launch(void* const* d_in, const int* in_sizes, int n_in,
                              void* d_out, int out_size) {
    const float* x     = (const float*)d_in[0];
    const float* gamma = (const float*)d_in[1];
    float* out         = (float*)d_out;

    cudaFuncSetAttribute(attn_mma_kernel, cudaFuncAttributeMaxDynamicSharedMemorySize, SMEM_TOTAL);

    prep_kernel<<<dim3(NTOK / 64, BATCH), 256>>>(x);
    attn_mma_kernel<<<dim3(NTOK / BM, BATCH), 128, SMEM_TOTAL>>>(x, gamma, out);
}

// round 17
// speedup vs baseline: 1.2050x; 1.0422x over previous
#include <cuda_runtime.h>
#include <cuda_bf16.h>
#include <stdint.h>

// Fused self-attention (Q=K=V=x), B=8, N=4096, C=64, fp32 in/out.
// out = gamma * softmax(x x^T) x + x
// Single-split bf16 HMMA flash attention. Fixed per-row softmax reference
// m_i = ||x_i||^2; consistent weights -> errors cancel; diagonal repaired
// exactly in epilogue. Schraudolph bf16 exp; l via ones-MMA; Q hoisted;
// per-warp adaptive tile skip (sound: total skipped weight <= 1e-9/row-tile).
// R17: 8 warps x 16 rows (256 thr, occ 2) -> 16 warps/SM for latency hiding.

#define NTOK   4096
#define CDIM   64
#define BM     128
#define BN     64
#define NTILES (NTOK / BN)
#define BATCH  8

#define EXPA   184.6650558f
#define MAGICF 12582912.0f            // 1.5 * 2^23
#define EXPB   (MAGICF + 16249.0f)
#define YTHR   (MAGICF + 12400.0f)    // ~1e-9 weight threshold

// ---------------- device scratch ----------------
__device__ __nv_bfloat16 g_xh[BATCH * (size_t)NTOK * CDIM];
__device__ float         g_sd[BATCH * NTOK];

// ---------------- helpers ----------------
__device__ __forceinline__ uint32_t smem_u32(const void* p) {
    uint32_t a;
    asm("{ .reg .u64 t; cvta.to.shared.u64 t, %1; cvt.u32.u64 %0, t; }" : "=r"(a) : "l"(p));
    return a;
}
__device__ __forceinline__ uint32_t pkbf(float lo, float hi) {
    uint32_t r;
    asm("cvt.rn.satfinite.bf16x2.f32 %0, %1, %2;" : "=r"(r) : "f"(hi), "f"(lo));
    return r;
}
__device__ __forceinline__ uint32_t prmt5410(uint32_t a, uint32_t b) {
    uint32_t r;
    asm("prmt.b32 %0, %1, %2, 0x5410;" : "=r"(r) : "r"(a), "r"(b));
    return r;
}
__device__ __forceinline__ float lo2f(uint32_t u) { return __uint_as_float(u << 16); }
__device__ __forceinline__ float hi2f(uint32_t u) { return __uint_as_float(u & 0xFFFF0000u); }

#define SWZ(o) ((o) ^ (((o) >> 3) & 0x70))

#define LDSM4(r0, r1, r2, r3, addr) \
    asm volatile("ldmatrix.sync.aligned.m8n8.x4.shared.b16 {%0,%1,%2,%3}, [%4];" \
                 : "=r"(r0), "=r"(r1), "=r"(r2), "=r"(r3) : "r"(addr))
#define LDSM4T(r0, r1, r2, r3, addr) \
    asm volatile("ldmatrix.sync.aligned.m8n8.x4.trans.shared.b16 {%0,%1,%2,%3}, [%4];" \
                 : "=r"(r0), "=r"(r1), "=r"(r2), "=r"(r3) : "r"(addr))
#define MMA(d, a0, a1, a2, a3, b0, b1) \
    asm volatile("mma.sync.aligned.m16n8k16.row.col.f32.bf16.bf16.f32 " \
                 "{%0,%1,%2,%3}, {%4,%5,%6,%7}, {%8,%9}, {%0,%1,%2,%3};" \
                 : "+f"((d)[0]), "+f"((d)[1]), "+f"((d)[2]), "+f"((d)[3]) \
                 : "r"(a0), "r"(a1), "r"(a2), "r"(a3), "r"(b0), "r"(b1))

__device__ __forceinline__ void cp16(uint32_t dst, const void* src) {
    asm volatile("cp.async.cg.shared.global [%0], [%1], 16;" :: "r"(dst), "l"(src) : "memory");
}
#define CP_COMMIT() asm volatile("cp.async.commit_group;" ::: "memory")
#define CP_WAIT0()  asm volatile("cp.async.wait_group 0;" ::: "memory")

// ---------------- smem layout ----------------
#define QH_OFF 0            // 16 KB : Q tile, SW128 (read once into registers)
#define KH_OFF 16384        // 2 x 8 KB : K tile double buffer
#define SMEM_TOTAL 32768

// ---------------- prep: bf16 hi + selfdot ----------------
__global__ __launch_bounds__(256) void prep_kernel(const float* __restrict__ x) {
    __shared__ float sx[64][65];
    const int b   = blockIdx.y;
    const int n0  = blockIdx.x * 64;
    const int tid = threadIdx.x;
    const float* xb = x + ((size_t)b * NTOK + n0) * CDIM;

    #pragma unroll
    for (int i = 0; i < 4; ++i) {
        int ch  = tid + 256 * i;
        int row = ch >> 4, g = ch & 15;
        float4 v = *(const float4*)(xb + row * CDIM + 4 * g);
        sx[row][4 * g + 0] = v.x; sx[row][4 * g + 1] = v.y;
        sx[row][4 * g + 2] = v.z; sx[row][4 * g + 3] = v.w;
        uint32_t hp0 = pkbf(v.x, v.y), hp1 = pkbf(v.z, v.w);
        size_t idx = ((size_t)b * NTOK + n0 + row) * CDIM + 4 * g;
        *(uint2*)(g_xh + idx) = make_uint2(hp0, hp1);
    }
    __syncthreads();
    if (tid < 64) {
        float s = 0.f;
        #pragma unroll
        for (int c = 0; c < 64; ++c) { float v = sx[tid][c]; s += v * v; }
        g_sd[b * NTOK + n0 + tid] = s;
    }
}

// ---------------- main attention kernel ----------------
__global__ __launch_bounds__(256, 2)
void attn_mma_kernel(const float* __restrict__ x, const float* __restrict__ gamma,
                     float* __restrict__ out) {
    extern __shared__ char smem[];
    const uint32_t sb = smem_u32(smem);
    const int tid = threadIdx.x, w = tid >> 5, lane = tid & 31;
    const int b = blockIdx.y, m0 = blockIdx.x * BM;
    const __nv_bfloat16* xh = g_xh + (size_t)b * NTOK * CDIM;

    // ---- Q tile, SW128-swizzled ----
    #pragma unroll
    for (int i = 0; i < 4; ++i) {
        int ch = tid + 256 * i;
        int row = ch >> 3, g = ch & 7;
        *(uint4*)(smem + QH_OFF + SWZ(row * 128 + 16 * g)) =
            *(const uint4*)(xh + (size_t)(m0 + row) * CDIM + 8 * g);
    }
    // ---- K tile 0 ----
    const int prow = tid >> 3, pg = tid & 7;   // 32 rows x 8 groups per pass
    #pragma unroll
    for (int i = 0; i < 2; ++i) {
        int row = prow + 32 * i;
        *(uint4*)(smem + KH_OFF + SWZ(row * 128 + 16 * pg)) =
            *(const uint4*)(xh + (size_t)row * CDIM + 8 * pg);
    }

    float o[8][4];
    #pragma unroll
    for (int j = 0; j < 8; ++j)
        #pragma unroll
        for (int v = 0; v < 4; ++v) o[j][v] = 0.f;
    float lacc[4] = {0.f, 0.f, 0.f, 0.f};

    const int r = lane >> 2;
    const float bmA = EXPB - g_sd[b * NTOK + m0 + w * 16 + r]     * EXPA;
    const float bmB = EXPB - g_sd[b * NTOK + m0 + w * 16 + r + 8] * EXPA;

    // diagonal-capture
    float cA = 0.f, cB = 0.f;
    const int  td  = (m0 + w * 16) >> 6;       // k-tile holding this warp's diag
    const int  fdA = 2 * (w & 3);              // rows-A diag col-block
    const int  fdB = fdA + 1;                  // rows-B diag col-block
    const bool cmatch = (2 * (lane & 3)) == (r & 6);
    const int  vsel   = r & 1;

#define CAPTURE(f_, p0_, p1_)                                            \
    if (dtile && cmatch) {                                               \
        if ((f_) == fdA) cA = vsel ? hi2f(p0_) : lo2f(p0_);              \
        if ((f_) == fdB) cB = vsel ? hi2f(p1_) : lo2f(p1_);              \
    }

    const int qrow0 = w * 16 + (lane & 15);
    const uint32_t aq_sel = (uint32_t)((lane >> 4) * 16);
    const uint32_t aq_b0 = (uint32_t)(qrow0 * 128);
    const uint32_t aq_x0 = (uint32_t)((qrow0 << 4) & 0x70);
    const uint32_t krl    = (uint32_t)(((((lane >> 4) & 1) * 8) + (lane & 7)) * 128);
    const uint32_t bk_sel = (uint32_t)(((lane >> 3) & 1) * 16);
    const uint32_t kx     = (uint32_t)((lane & 7) << 4);
    const uint32_t vrl  = (uint32_t)((lane & 15) * 128);
    const uint32_t jsel = (uint32_t)(((lane >> 4) & 1) * 16);
    const uint32_t ONES = 0x3F803F80u;

    __syncthreads();

    // ---- hoist Q fragments (tile-invariant; 16 regs) ----
    uint32_t qf[4][4];
    #pragma unroll
    for (int kc = 0; kc < 4; ++kc)
        LDSM4(qf[kc][0], qf[kc][1], qf[kc][2], qf[kc][3],
              sb + QH_OFF + aq_b0 + (((uint32_t)(kc * 32) + aq_sel) ^ aq_x0));

    for (int t = 0; t < NTILES; ++t) {
        const uint32_t KHc = KH_OFF + (uint32_t)(t & 1) * 8192;
        const bool dtile = (t == td);

        // ---- prefetch next K tile ----
        if (t + 1 < NTILES) {
            const uint32_t nb = KH_OFF + (uint32_t)((t + 1) & 1) * 8192;
            const __nv_bfloat16* kh = xh + (size_t)(t + 1) * BN * CDIM;
            #pragma unroll
            for (int i = 0; i < 2; ++i) {
                int row = prow + 32 * i;
                cp16(sb + nb + SWZ(row * 128 + 16 * pg), kh + (size_t)row * CDIM + 8 * pg);
            }
        }
        CP_COMMIT();

        float s[8][4];
        #pragma unroll
        for (int f = 0; f < 8; ++f)
            #pragma unroll
            for (int v = 0; v < 4; ++v) s[f][v] = 0.f;

        // ---- S = Q K^T (Q from registers) ----
        #pragma unroll
        for (int kc = 0; kc < 4; ++kc) {
            const uint32_t colk = ((uint32_t)(kc * 32) + bk_sel) ^ kx;
            #pragma unroll
            for (int h = 0; h < 2; ++h) {
                uint32_t kh[8];
                const uint32_t ka = sb + KHc + (uint32_t)(h * 4096) + krl + colk;
                LDSM4(kh[0], kh[1], kh[2], kh[3], ka);
                LDSM4(kh[4], kh[5], kh[6], kh[7], ka + 2048);
                #pragma unroll
                for (int j = 0; j < 4; ++j)
                    MMA(s[h * 4 + j], qf[kc][0], qf[kc][1], qf[kc][2], qf[kc][3],
                        kh[2 * j], kh[2 * j + 1]);
            }
        }

        // ---- warp-level activity check ----
        float ma = fmaxf(s[0][0], s[0][1]);
        float mb = fmaxf(s[0][2], s[0][3]);
        #pragma unroll
        for (int f = 1; f < 8; ++f) {
            ma = fmaxf(ma, fmaxf(s[f][0], s[f][1]));
            mb = fmaxf(mb, fmaxf(s[f][2], s[f][3]));
        }
        float wmax = fmaxf(fmaf(ma, EXPA, bmA), fmaf(mb, EXPA, bmB));
        #pragma unroll
        for (int off = 16; off; off >>= 1)
            wmax = fmaxf(wmax, __shfl_xor_sync(0xffffffffu, wmax, off));

        if (wmax >= YTHR) {
            // ---- exp via Schraudolph ----
            uint32_t ph[8][2];
            #pragma unroll
            for (int f = 0; f < 8; ++f) {
                float y0 = fmaxf(fmaf(s[f][0], EXPA, bmA), MAGICF);
                float y1 = fmaxf(fmaf(s[f][1], EXPA, bmA), MAGICF);
                float y2 = fmaxf(fmaf(s[f][2], EXPA, bmB), MAGICF);
                float y3 = fmaxf(fmaf(s[f][3], EXPA, bmB), MAGICF);
                ph[f][0] = prmt5410(__float_as_uint(y0), __float_as_uint(y1));
                ph[f][1] = prmt5410(__float_as_uint(y2), __float_as_uint(y3));
                CAPTURE(f, ph[f][0], ph[f][1]);
            }

            // ---- O += P V ; l += P * ones ----
            #pragma unroll
            for (int kc = 0; kc < 4; ++kc) {
                const uint32_t p0 = ph[2 * kc][0], p1 = ph[2 * kc][1];
                const uint32_t p2 = ph[2 * kc + 1][0], p3 = ph[2 * kc + 1][1];
                MMA(lacc, p0, p1, p2, p3, ONES, ONES);
                const uint32_t vbase = sb + KHc + (uint32_t)(kc * 2048) + vrl;
                #pragma unroll
                for (int h = 0; h < 2; ++h) {
                    uint32_t vh[8];
                    const uint32_t cAo = ((uint32_t)(h * 64) + jsel) ^ kx;
                    const uint32_t cBo = ((uint32_t)(h * 64 + 32) + jsel) ^ kx;
                    LDSM4T(vh[0], vh[1], vh[2], vh[3], vbase + cAo);
                    LDSM4T(vh[4], vh[5], vh[6], vh[7], vbase + cBo);
                    #pragma unroll
                    for (int j = 0; j < 4; ++j)
                        MMA(o[h * 4 + j], p0, p1, p2, p3, vh[2 * j], vh[2 * j + 1]);
                }
            }
        }

        CP_WAIT0();
        __syncthreads();
    }

    // ---- epilogue: l from ones-MMA; exact diagonal repair ----
    const float gm = gamma[0];
    const int c0 = 2 * (lane & 3);
    const float la = lacc[0];
    const float lb = lacc[2];
    float a1 = cA, b1 = cB;
    #pragma unroll
    for (int off = 1; off <= 2; off <<= 1) {
        a1 += __shfl_xor_sync(0xffffffffu, a1, off);
        b1 += __shfl_xor_sync(0xffffffffu, b1, off);
    }
    const float sA = gm / la, sB = gm / lb;
    const size_t rowA = ((size_t)b * NTOK + m0 + w * 16 + r) * CDIM;
    const size_t rowB = rowA + 8 * CDIM;
    #pragma unroll
    for (int j = 0; j < 8; ++j) {
        const int c = j * 8 + c0;
        float2 xa  = *(const float2*)(x + rowA + c);
        float2 xb2 = *(const float2*)(x + rowB + c);
        uint32_t pa = pkbf(xa.x, xa.y);
        uint32_t pb = pkbf(xb2.x, xb2.y);
        float oax = o[j][0] + a1 * (xa.x  - lo2f(pa));
        float oay = o[j][1] + a1 * (xa.y  - hi2f(pa));
        float obx = o[j][2] + b1 * (xb2.x - lo2f(pb));
        float oby = o[j][3] + b1 * (xb2.y - hi2f(pb));
        float2 oa, ob;
        oa.x = sA * oax + xa.x;  oa.y = sA * oay + xa.y;
        ob.x = sB * obx + xb2.x; ob.y = sB * oby + xb2.y;
        *(float2*)(out + rowA + c) = oa;
        *(float2*)(out + rowB + c) = ob;
    }
}

// ---------------- launch ----------------
extern "C" void kernel_launch(void* const* d_in, const int* in_sizes, int n_in,
                              void* d_out, int out_size) {
    const float* x     = (const float*)d_in[0];
    const float* gamma = (const float*)d_in[1];
    float* out         = (float*)d_out;

    cudaFuncSetAttribute(attn_mma_kernel, cudaFuncAttributeMaxDynamicSharedMemorySize, SMEM_TOTAL);

    prep_kernel<<<dim3(NTOK / 64, BATCH), 256>>>(x);
    attn_mma_kernel<<<dim3(NTOK / BM, BATCH), 256, SMEM_TOTAL>>>(x, gamma, out);
}